// round 10
// baseline (speedup 1.0000x reference)
#include <cuda_runtime.h>
#include <cuda_bf16.h>
#include <cstdint>
#include <math.h>

#define BSZ  4
#define NSEQ 2048
#define EMB  1024
#define HNUM 16
#define DH   64
#define SCALE 0.125f  // 1/sqrt(64)
#define NTOK (BSZ * NSEQ)          // 8192
#define XELEM (NTOK * EMB)         // 8388608
#define WELEM (EMB * EMB)          // 1048576

// ---------------- Scratch (device globals — no allocation allowed) ----------
__device__ float g_Q[XELEM];
__device__ float g_K[XELEM];
__device__ float g_V[XELEM];
// bf16 hi/lo pre-split operands
__device__ __align__(16) uint16_t g_Xh[3][XELEM];
__device__ __align__(16) uint16_t g_Xl[3][XELEM];
__device__ __align__(16) uint16_t g_Wh[4][WELEM];
__device__ __align__(16) uint16_t g_Wl[4][WELEM];
__device__ __align__(16) uint16_t g_Ch[XELEM];
__device__ __align__(16) uint16_t g_Cl[XELEM];

// ---------------- helpers ----------------------------------------------------
__device__ __forceinline__ float to_tf32(float x) {
    float r;
    asm("cvt.rna.tf32.f32 %0, %1;" : "=f"(r) : "f"(x));
    return r;
}

__device__ __forceinline__ void mma_tf32(float* d, const uint32_t* a, const uint32_t* b) {
    asm volatile(
        "mma.sync.aligned.m16n8k8.row.col.f32.tf32.tf32.f32 "
        "{%0,%1,%2,%3}, {%4,%5,%6,%7}, {%8,%9}, {%0,%1,%2,%3};"
        : "+f"(d[0]), "+f"(d[1]), "+f"(d[2]), "+f"(d[3])
        : "r"(a[0]), "r"(a[1]), "r"(a[2]), "r"(a[3]), "r"(b[0]), "r"(b[1]));
}

__device__ __forceinline__ void mma_bf16(float* d, const uint32_t* a, const uint32_t* b) {
    asm volatile(
        "mma.sync.aligned.m16n8k16.row.col.f32.bf16.bf16.f32 "
        "{%0,%1,%2,%3}, {%4,%5,%6,%7}, {%8,%9}, {%0,%1,%2,%3};"
        : "+f"(d[0]), "+f"(d[1]), "+f"(d[2]), "+f"(d[3])
        : "r"(a[0]), "r"(a[1]), "r"(a[2]), "r"(a[3]), "r"(b[0]), "r"(b[1]));
}

__device__ __forceinline__ void split2(float f0, float f1, uint32_t& hi, uint32_t& lo) {
    __nv_bfloat16 h0 = __float2bfloat16_rn(f0);
    __nv_bfloat16 h1 = __float2bfloat16_rn(f1);
    float r0 = f0 - __bfloat162float(h0);
    float r1 = f1 - __bfloat162float(h1);
    __nv_bfloat16 l0 = __float2bfloat16_rn(r0);
    __nv_bfloat16 l1 = __float2bfloat16_rn(r1);
    hi = (uint32_t)__bfloat16_as_ushort(h0) | ((uint32_t)__bfloat16_as_ushort(h1) << 16);
    lo = (uint32_t)__bfloat16_as_ushort(l0) | ((uint32_t)__bfloat16_as_ushort(l1) << 16);
}

__device__ __forceinline__ void cpasync16(uint32_t saddr, const void* g) {
    asm volatile("cp.async.cg.shared.global [%0], [%1], 16;" :: "r"(saddr), "l"(g));
}
#define CP_COMMIT() asm volatile("cp.async.commit_group;")
#define CP_WAIT1()  asm volatile("cp.async.wait_group 1;")

// ---------------- split kernels ----------------------------------------------
__global__ __launch_bounds__(256)
void split_x(const float* __restrict__ xq, const float* __restrict__ xk,
             const float* __restrict__ xv)
{
    const int z = blockIdx.z;
    const float4* in = (const float4*)(z == 0 ? xq : (z == 1 ? xk : xv));
    uint2* oh = (uint2*)g_Xh[z];
    uint2* ol = (uint2*)g_Xl[z];
    const int i = blockIdx.x * 256 + threadIdx.x;
    float4 f = in[i];
    uint32_t h0, l0, h1, l1;
    split2(f.x, f.y, h0, l0);
    split2(f.z, f.w, h1, l1);
    oh[i] = make_uint2(h0, h1);
    ol[i] = make_uint2(l0, l1);
}

__global__ __launch_bounds__(256)
void split_w(const float* __restrict__ Wq, const float* __restrict__ Wk,
             const float* __restrict__ Wv, const float* __restrict__ Wo)
{
    const int z = blockIdx.z;
    const float4* in = (const float4*)(z == 0 ? Wq : (z == 1 ? Wk : (z == 2 ? Wv : Wo)));
    uint2* oh = (uint2*)g_Wh[z];
    uint2* ol = (uint2*)g_Wl[z];
    const int i = blockIdx.x * 256 + threadIdx.x;
    float4 f = in[i];
    uint32_t h0, l0, h1, l1;
    split2(f.x, f.y, h0, l0);
    split2(f.z, f.w, h1, l1);
    oh[i] = make_uint2(h0, h1);
    ol[i] = make_uint2(l0, l1);
}

// ===========================================================================
// bf16x2-split GEMM (3 MMAs per k16), pre-split operands, cp.async 2-stage.
// CTA 128x128, BK=32, 256 threads = 8 warps (4M x 2N), warp tile 32x64.
// pitch 20 u32 (40 bf16) => conflict-free fragment LDS.
// ===========================================================================
#define BKG 32
#define GP 20                         // tile pitch in u32 units
#define GBUF (128 * GP)               // per-array buffer (u32)
#define ARRB (GBUF * 4)               // per-array bytes (10240)
#define STAGEB (4 * ARRB)             // per-stage bytes (40960)
#define GEMM_SMEM (2 * STAGEB)        // 81920 bytes

template <bool BIAS>
__device__ __forceinline__
void gemm_bf_body(const uint16_t* __restrict__ Ah, const uint16_t* __restrict__ Al,
                  const uint16_t* __restrict__ Bh, const uint16_t* __restrict__ Bl,
                  const float* __restrict__ bias, float* __restrict__ C,
                  int M, int Ncol, int K)
{
    extern __shared__ uint32_t su[];

    const int tid = threadIdx.x;
    const int wid = tid >> 5;
    const int lane = tid & 31;
    const int g = lane >> 2;
    const int t = lane & 3;
    const int wm = wid >> 1;
    const int wn = wid & 1;
    const int m0 = blockIdx.y * 128;
    const int n0 = blockIdx.x * 128;

    // Staging map: thread covers row (tid>>1), 16 bf16 at col (tid&1)*16 per array.
    const int srow = tid >> 1;
    const int scol = (tid & 1) * 16;
    const uint16_t* gAh = Ah + (size_t)(m0 + srow) * K + scol;
    const uint16_t* gAl = Al + (size_t)(m0 + srow) * K + scol;
    const uint16_t* gBh = Bh + (size_t)(n0 + srow) * K + scol;
    const uint16_t* gBl = Bl + (size_t)(n0 + srow) * K + scol;
    const uint32_t sbase = (uint32_t)__cvta_generic_to_shared(su);
    const uint32_t soff = (uint32_t)(srow * GP + (tid & 1) * 8) * 4;

#define ISSUE(cc, st) do {                                   \
    const int _k0 = (cc) * BKG;                              \
    uint32_t _sa = sbase + (st) * STAGEB + soff;             \
    cpasync16(_sa + 0 * ARRB,      gAh + _k0);               \
    cpasync16(_sa + 0 * ARRB + 16, gAh + _k0 + 8);           \
    cpasync16(_sa + 1 * ARRB,      gAl + _k0);               \
    cpasync16(_sa + 1 * ARRB + 16, gAl + _k0 + 8);           \
    cpasync16(_sa + 2 * ARRB,      gBh + _k0);               \
    cpasync16(_sa + 2 * ARRB + 16, gBh + _k0 + 8);           \
    cpasync16(_sa + 3 * ARRB,      gBl + _k0);               \
    cpasync16(_sa + 3 * ARRB + 16, gBl + _k0 + 8);           \
} while (0)

    float d[2][8][4];
#pragma unroll
    for (int i = 0; i < 2; i++)
#pragma unroll
        for (int j = 0; j < 8; j++)
#pragma unroll
            for (int q = 0; q < 4; q++) d[i][j][q] = 0.f;

    const int nchunks = K / BKG;   // 32
    ISSUE(0, 0); CP_COMMIT();
    ISSUE(1, 1); CP_COMMIT();

    for (int c = 0; c < nchunks; ++c) {
        CP_WAIT1();
        __syncthreads();

        const uint32_t* bAh = su + (c & 1) * (STAGEB / 4);
        const uint32_t* bAl = bAh + GBUF;
        const uint32_t* bBh = bAh + 2 * GBUF;
        const uint32_t* bBl = bAh + 3 * GBUF;

#pragma unroll
        for (int ks = 0; ks < 2; ks++) {
            const int kb = ks * 8;
            uint32_t ah[2][4], al[2][4];
#pragma unroll
            for (int mf = 0; mf < 2; mf++) {
                const int roff = (wm * 32 + mf * 16 + g) * GP + kb + t;
                ah[mf][0] = bAh[roff];
                ah[mf][1] = bAh[roff + 8 * GP];
                ah[mf][2] = bAh[roff + 4];
                ah[mf][3] = bAh[roff + 8 * GP + 4];
                al[mf][0] = bAl[roff];
                al[mf][1] = bAl[roff + 8 * GP];
                al[mf][2] = bAl[roff + 4];
                al[mf][3] = bAl[roff + 8 * GP + 4];
            }
#pragma unroll
            for (int half = 0; half < 2; half++) {
                uint32_t bh_[4][2], bl_[4][2];
#pragma unroll
                for (int nh = 0; nh < 4; nh++) {
                    const int nf = half * 4 + nh;
                    const int coff = (wn * 64 + nf * 8 + g) * GP + kb + t;
                    bh_[nh][0] = bBh[coff];
                    bh_[nh][1] = bBh[coff + 4];
                    bl_[nh][0] = bBl[coff];
                    bl_[nh][1] = bBl[coff + 4];
                }
#pragma unroll
                for (int mf = 0; mf < 2; mf++)
#pragma unroll
                    for (int nh = 0; nh < 4; nh++) {
                        const int nf = half * 4 + nh;
                        mma_bf16(d[mf][nf], ah[mf], bh_[nh]);
                        mma_bf16(d[mf][nf], ah[mf], bl_[nh]);
                        mma_bf16(d[mf][nf], al[mf], bh_[nh]);
                    }
            }
        }
        __syncthreads();
        if (c + 2 < nchunks) ISSUE(c + 2, c & 1);
        CP_COMMIT();
    }
#undef ISSUE

    // ---- Epilogue ----
#pragma unroll
    for (int mf = 0; mf < 2; mf++) {
        const int r0 = m0 + wm * 32 + mf * 16 + g;
#pragma unroll
        for (int nf = 0; nf < 8; nf++) {
            const int col = n0 + wn * 64 + nf * 8 + 2 * t;
            float2 v0, v1;
            v0.x = d[mf][nf][0]; v0.y = d[mf][nf][1];
            v1.x = d[mf][nf][2]; v1.y = d[mf][nf][3];
            if (BIAS) {
                const float2 bv = *(const float2*)&bias[col];
                v0.x += bv.x; v0.y += bv.y;
                v1.x += bv.x; v1.y += bv.y;
            }
            *(float2*)&C[(size_t)r0 * Ncol + col] = v0;
            *(float2*)&C[(size_t)(r0 + 8) * Ncol + col] = v1;
        }
    }
}

// Fused Q/K/V projection: blockIdx.z selects which GEMM.
__global__ __launch_bounds__(256, 2)
void qkv_gemm(float* __restrict__ q, float* __restrict__ k, float* __restrict__ v)
{
    const int z = blockIdx.z;
    float* C = (z == 0) ? q : (z == 1) ? k : v;
    gemm_bf_body<false>(g_Xh[z], g_Xl[z], g_Wh[z], g_Wl[z], nullptr, C,
                        NTOK, EMB, EMB);
}

__global__ __launch_bounds__(256, 2)
void out_gemm(const float* __restrict__ bias, float* __restrict__ C)
{
    gemm_bf_body<true>(g_Ch, g_Cl, g_Wh[3], g_Wl[3], bias, C, NTOK, EMB, EMB);
}

// ===========================================================================
// Tensor-core flash attention (causal), tf32 HMMA.
// Epilogue writes context pre-split into g_Ch / g_Cl (bf16 hi/lo).
// ===========================================================================
#define ATT_SMEM ((3 * 64 * 68 + 64 * 72) * 4)

__global__ __launch_bounds__(128)
void attn_tc(const float* __restrict__ Q, const float* __restrict__ K,
             const float* __restrict__ V)
{
    extern __shared__ float sm[];
    float* sQ = sm;                  // [64][68] tf32
    float* sK = sm + 64 * 68;        // [64][68] tf32
    float* sP = sm + 2 * 64 * 68;    // [64][68] tf32 probs
    float* sV = sm + 3 * 64 * 68;    // [64][72] tf32

    const int tid = threadIdx.x;
    const int w = tid >> 5;
    const int lane = tid & 31;
    const int g = lane >> 2;
    const int t = lane & 3;
    const int qt = blockIdx.x;
    const int bh = blockIdx.y;
    const int b = bh >> 4, h = bh & 15;
    const int base = (b * NSEQ) * EMB + h * DH;
    const int qbase = qt * 64;

    const int r0 = w * 16 + g;
    const int r1 = r0 + 8;

#pragma unroll
    for (int i = 0; i < 8; i++) {
        int idx = i * 128 + tid;
        int row = idx >> 4, c4 = idx & 15;
        float4 f = *(const float4*)&Q[base + (qbase + row) * EMB + c4 * 4];
        f.x = to_tf32(f.x); f.y = to_tf32(f.y);
        f.z = to_tf32(f.z); f.w = to_tf32(f.w);
        *(float4*)(sQ + row * 68 + c4 * 4) = f;
    }

    float o[8][4];
#pragma unroll
    for (int nf = 0; nf < 8; nf++)
#pragma unroll
        for (int q = 0; q < 4; q++) o[nf][q] = 0.f;
    float mr0 = -INFINITY, mr1 = -INFINITY;
    float lr0 = 0.f, lr1 = 0.f;

    for (int j = 0; j <= qt; j++) {
        __syncthreads();

#pragma unroll
        for (int i = 0; i < 8; i++) {
            int idx = i * 128 + tid;
            int row = idx >> 4, c4 = idx & 15;
            float4 fk = *(const float4*)&K[base + (j * 64 + row) * EMB + c4 * 4];
            float4 fv = *(const float4*)&V[base + (j * 64 + row) * EMB + c4 * 4];
            fk.x = to_tf32(fk.x); fk.y = to_tf32(fk.y);
            fk.z = to_tf32(fk.z); fk.w = to_tf32(fk.w);
            fv.x = to_tf32(fv.x); fv.y = to_tf32(fv.y);
            fv.z = to_tf32(fv.z); fv.w = to_tf32(fv.w);
            *(float4*)(sK + row * 68 + c4 * 4) = fk;
            *(float4*)(sV + row * 72 + c4 * 4) = fv;
        }
        __syncthreads();

        float s[8][4];
#pragma unroll
        for (int nf = 0; nf < 8; nf++)
#pragma unroll
            for (int q = 0; q < 4; q++) s[nf][q] = 0.f;
#pragma unroll
        for (int kb8 = 0; kb8 < 8; kb8++) {
            const int kb = kb8 * 8;
            uint32_t a[4];
            {
                const float* bp = sQ + r0 * 68 + kb + t;
                a[0] = __float_as_uint(bp[0]);
                a[1] = __float_as_uint(bp[8 * 68]);
                a[2] = __float_as_uint(bp[4]);
                a[3] = __float_as_uint(bp[8 * 68 + 4]);
            }
#pragma unroll
            for (int nf = 0; nf < 8; nf++) {
                uint32_t bf[2];
                const float* bp = sK + (nf * 8 + g) * 68 + kb + t;
                bf[0] = __float_as_uint(bp[0]);
                bf[1] = __float_as_uint(bp[4]);
                mma_tf32(s[nf], a, bf);
            }
        }

        const bool diag = (j == qt);
#pragma unroll
        for (int nf = 0; nf < 8; nf++) {
            const int c0 = nf * 8 + 2 * t;
            if (diag) {
                s[nf][0] = (c0 <= r0)     ? s[nf][0] * SCALE : -1e30f;
                s[nf][1] = (c0 + 1 <= r0) ? s[nf][1] * SCALE : -1e30f;
                s[nf][2] = (c0 <= r1)     ? s[nf][2] * SCALE : -1e30f;
                s[nf][3] = (c0 + 1 <= r1) ? s[nf][3] * SCALE : -1e30f;
            } else {
                s[nf][0] *= SCALE; s[nf][1] *= SCALE;
                s[nf][2] *= SCALE; s[nf][3] *= SCALE;
            }
        }

        float mt0 = -INFINITY, mt1 = -INFINITY;
#pragma unroll
        for (int nf = 0; nf < 8; nf++) {
            mt0 = fmaxf(mt0, fmaxf(s[nf][0], s[nf][1]));
            mt1 = fmaxf(mt1, fmaxf(s[nf][2], s[nf][3]));
        }
        mt0 = fmaxf(mt0, __shfl_xor_sync(0xffffffffu, mt0, 1));
        mt0 = fmaxf(mt0, __shfl_xor_sync(0xffffffffu, mt0, 2));
        mt1 = fmaxf(mt1, __shfl_xor_sync(0xffffffffu, mt1, 1));
        mt1 = fmaxf(mt1, __shfl_xor_sync(0xffffffffu, mt1, 2));
        const float mn0 = fmaxf(mr0, mt0);
        const float mn1 = fmaxf(mr1, mt1);
        const float al0 = __expf(mr0 - mn0);
        const float al1 = __expf(mr1 - mn1);
        float sum0 = 0.f, sum1 = 0.f;
#pragma unroll
        for (int nf = 0; nf < 8; nf++) {
            s[nf][0] = __expf(s[nf][0] - mn0);
            s[nf][1] = __expf(s[nf][1] - mn0);
            s[nf][2] = __expf(s[nf][2] - mn1);
            s[nf][3] = __expf(s[nf][3] - mn1);
            sum0 += s[nf][0] + s[nf][1];
            sum1 += s[nf][2] + s[nf][3];
        }
        sum0 += __shfl_xor_sync(0xffffffffu, sum0, 1);
        sum0 += __shfl_xor_sync(0xffffffffu, sum0, 2);
        sum1 += __shfl_xor_sync(0xffffffffu, sum1, 1);
        sum1 += __shfl_xor_sync(0xffffffffu, sum1, 2);
        lr0 = lr0 * al0 + sum0;
        lr1 = lr1 * al1 + sum1;
        mr0 = mn0; mr1 = mn1;
#pragma unroll
        for (int nf = 0; nf < 8; nf++) {
            o[nf][0] *= al0; o[nf][1] *= al0;
            o[nf][2] *= al1; o[nf][3] *= al1;
        }

#pragma unroll
        for (int nf = 0; nf < 8; nf++) {
            const int c0 = nf * 8 + 2 * t;
            float2 p0, p1;
            p0.x = to_tf32(s[nf][0]); p0.y = to_tf32(s[nf][1]);
            p1.x = to_tf32(s[nf][2]); p1.y = to_tf32(s[nf][3]);
            *(float2*)(sP + r0 * 68 + c0) = p0;
            *(float2*)(sP + r1 * 68 + c0) = p1;
        }
        __syncwarp();
        __syncthreads();

#pragma unroll
        for (int kb8 = 0; kb8 < 8; kb8++) {
            const int kb = kb8 * 8;
            uint32_t a[4];
            {
                const float* bp = sP + r0 * 68 + kb + t;
                a[0] = __float_as_uint(bp[0]);
                a[1] = __float_as_uint(bp[8 * 68]);
                a[2] = __float_as_uint(bp[4]);
                a[3] = __float_as_uint(bp[8 * 68 + 4]);
            }
#pragma unroll
            for (int nf = 0; nf < 8; nf++) {
                uint32_t bf[2];
                bf[0] = __float_as_uint(sV[(kb + t) * 72 + nf * 8 + g]);
                bf[1] = __float_as_uint(sV[(kb + t + 4) * 72 + nf * 8 + g]);
                mma_tf32(o[nf], a, bf);
            }
        }
    }

    // ---- epilogue: normalize + bf16 hi/lo split directly into g_Ch/g_Cl ----
    uint32_t* Ch = (uint32_t*)g_Ch;
    uint32_t* Cl = (uint32_t*)g_Cl;
    const float inv0 = 1.f / lr0;
    const float inv1 = 1.f / lr1;
#pragma unroll
    for (int nf = 0; nf < 8; nf++) {
        const int c0 = nf * 8 + 2 * t;
        uint32_t hi, lo;
        const int i0 = base + (qbase + r0) * EMB + c0;
        split2(o[nf][0] * inv0, o[nf][1] * inv0, hi, lo);
        Ch[i0 >> 1] = hi; Cl[i0 >> 1] = lo;
        const int i1 = base + (qbase + r1) * EMB + c0;
        split2(o[nf][2] * inv1, o[nf][3] * inv1, hi, lo);
        Ch[i1 >> 1] = hi; Cl[i1 >> 1] = lo;
    }
}

// ---------------------------------------------------------------------------
extern "C" void kernel_launch(void* const* d_in, const int* in_sizes, int n_in,
                              void* d_out, int out_size)
{
    const float* xq = (const float*)d_in[0];
    const float* xk = (const float*)d_in[1];
    const float* xv = (const float*)d_in[2];
    // d_in[3] = attn_mask (causal triu) — implemented analytically, ignored
    const float* Wq = (const float*)d_in[4];
    const float* Wk = (const float*)d_in[5];
    const float* Wv = (const float*)d_in[6];
    const float* Wo = (const float*)d_in[7];
    const float* bo = (const float*)d_in[8];
    float* out = (float*)d_out;

    float *q, *k, *v;
    cudaGetSymbolAddress((void**)&q, g_Q);
    cudaGetSymbolAddress((void**)&k, g_K);
    cudaGetSymbolAddress((void**)&v, g_V);

    cudaFuncSetAttribute(attn_tc, cudaFuncAttributeMaxDynamicSharedMemorySize,
                         ATT_SMEM);
    cudaFuncSetAttribute(qkv_gemm, cudaFuncAttributeMaxDynamicSharedMemorySize,
                         GEMM_SMEM);
    cudaFuncSetAttribute(out_gemm, cudaFuncAttributeMaxDynamicSharedMemorySize,
                         GEMM_SMEM);

    // Pre-split inputs and weights into bf16 hi/lo
    split_x<<<dim3(XELEM / 4 / 256, 1, 3), 256>>>(xq, xk, xv);
    split_w<<<dim3(WELEM / 4 / 256, 1, 4), 256>>>(Wq, Wk, Wv, Wo);

    dim3 gqkv(EMB / 128, NTOK / 128, 3);  // (8, 64, 3)
    qkv_gemm<<<gqkv, 256, GEMM_SMEM>>>(q, k, v);

    attn_tc<<<dim3(NSEQ / 64, BSZ * HNUM), 128, ATT_SMEM>>>(q, k, v);

    out_gemm<<<dim3(EMB / 128, NTOK / 128), 256, GEMM_SMEM>>>(bo, out);
}